// round 11
// baseline (speedup 1.0000x reference)
#include <cuda_runtime.h>
#include <cstdint>

#define H_CH 256
#define NST  64
#define LL   4096
#define NBATCH 16

typedef unsigned long long ull;

// Scratch (device global: allocation-free rule)
__device__ float2 g_Khat[H_CH * LL];   // hermitian part of K, pre-scaled by 1/L

__device__ __forceinline__ float2 cmul(float2 a, float2 b) {
    return make_float2(a.x * b.x - a.y * b.y, a.x * b.y + a.y * b.x);
}
__device__ __forceinline__ float2 cadd(float2 a, float2 b) {
    return make_float2(a.x + b.x, a.y + b.y);
}
__device__ __forceinline__ float2 csub(float2 a, float2 b) {
    return make_float2(a.x - b.x, a.y - b.y);
}

// ---- packed f32x2 helpers ----
__device__ __forceinline__ ull pk(float lo, float hi) {
    ull r; asm("mov.b64 %0,{%1,%2};" : "=l"(r) : "f"(lo), "f"(hi)); return r;
}
__device__ __forceinline__ void upk(ull v, float& lo, float& hi) {
    asm("mov.b64 {%0,%1},%2;" : "=f"(lo), "=f"(hi) : "l"(v));
}
__device__ __forceinline__ ull fma2(ull a, ull b, ull c) {
    ull d; asm("fma.rn.f32x2 %0,%1,%2,%3;" : "=l"(d) : "l"(a), "l"(b), "l"(c)); return d;
}

// Correctly-rounded float sin/cos via double polynomial.
// Needed so 1+cos / 1-cos cancellation sites match the float32 reference bitwise.
// Valid for ang in [-2*pi, 0].
__device__ __forceinline__ void sincos_acc(float angf, float* s, float* c) {
    double x  = (double)angf;
    double kd = rint(x * 0.63661977236758134308);   // x / (pi/2)
    double r  = x - kd * 1.5707963267948966;
    r        -= kd * 6.123233995736766e-17;
    int q = (int)kd;
    double r2 = r * r;
    double sr = r * (1.0 + r2 * (-1.6666666666666666e-01 + r2 * (8.3333333333333332e-03
                 + r2 * (-1.9841269841269841e-04 + r2 * 2.7557319223985893e-06))));
    double cr = 1.0 + r2 * (-0.5 + r2 * (4.1666666666666664e-02
                 + r2 * (-1.3888888888888889e-03 + r2 * (2.4801587301587302e-05
                 - r2 * 2.7557319223985888e-07))));
    double ss, cc;
    switch (q & 3) {
        case 0:  ss =  sr; cc =  cr; break;
        case 1:  ss =  cr; cc = -sr; break;
        case 2:  ss = -sr; cc = -cr; break;
        default: ss = -cr; cc =  sr; break;
    }
    *s = (float)ss;
    *c = (float)cc;
}

// ---------------------------------------------------------------------------
// Kernel 1: S4 DPLR frequency-domain kernel + FUSED Hermitian part.
// 4 l-values per thread: mirror pairs (g, 4096-g) and (1024+g, 3072-g).
// Shared tables stored PRE-PACKED as 64-bit f32x2 lanes (ulonglong2 ->
// LDS.128 -> two ready register pairs; zero pack MOVs in the loop).
// Denominator handled scalar:
//   dr = gr + (-lam.re); di = gi + (-lam.im)
//   inv = rcp(dr^2 + di^2);  w = (dr*inv, di*inv)
//   accA_s += w * (v.x,v.x)  ;  accB_s += w * (v.y,v.y)
//   sum_s  = (accA.lo + accB.hi) + i*(accB.lo - accA.hi)
// ---------------------------------------------------------------------------
struct alignas(16) Tab0 { float nlr, nli; ull pp2; };

__global__ __launch_bounds__(256)
void kgen(const float* __restrict__ Lre, const float* __restrict__ Lim,
          const float* __restrict__ Pre, const float* __restrict__ Pim,
          const float* __restrict__ Bre, const float* __restrict__ Bim,
          const float* __restrict__ Cre, const float* __restrict__ Cim,
          const float* __restrict__ lstep) {
    __shared__ Tab0       sT0[NST];   // (-lam.re, -lam.im, (pp,pp))
    __shared__ ulonglong2 sT1[NST];   // ((cb.x,cb.x), (cb.y,cb.y))  cb = conj(C)*B
    __shared__ ulonglong2 sT2[NST];   // conj(C)*P
    __shared__ ulonglong2 sT3[NST];   // conj(P)*B
    __shared__ float      s_tos;

    int h   = blockIdx.x >> 2;
    int seg = blockIdx.x & 3;
    int tid = threadIdx.x;

    if (tid < NST) {
        int idx = h * NST + tid;
        float lr = Lre[idx], li = Lim[idx];
        float pr = Pre[idx], pi = Pim[idx];
        float br = Bre[idx], bi = Bim[idx];
        float cr = Cre[idx], ci = Cim[idx];
        float cbx = cr * br + ci * bi, cby = cr * bi - ci * br;
        float cpx = cr * pr + ci * pi, cpy = cr * pi - ci * pr;
        float pbx = pr * br + pi * bi, pby = pr * bi - pi * br;
        float pp  = pr * pr + pi * pi;
        Tab0 t0; t0.nlr = -lr; t0.nli = -li; t0.pp2 = pk(pp, pp);
        sT0[tid] = t0;
        sT1[tid] = make_ulonglong2(pk(cbx, cbx), pk(cby, cby));
        sT2[tid] = make_ulonglong2(pk(cpx, cpx), pk(cpy, cpy));
        sT3[tid] = make_ulonglong2(pk(pbx, pbx), pk(pby, pby));
    }
    if (tid == 0) s_tos = 2.0f / __expf(lstep[h]);
    __syncthreads();
    float tos = s_tos;

    const float neg2pi = (float)(-6.283185307179586);

    // 4 l-values: pairs (gid, 4096-gid) [gid==0 -> (0,2048), both self-mirrored]
    //             and   (1024+gid, 3072-gid)
    int gid = seg * 256 + tid;          // 0..1023 per h
    int lv[4];
    lv[0] = gid;
    lv[1] = (gid == 0) ? 2048 : (LL - gid);
    lv[2] = 1024 + gid;
    lv[3] = 3072 - gid;
    bool selfm = (gid == 0);            // first pair: both bins self-mirrored

    float crv[4], civ[4];               // c = 2/(1+Omega)
    float grs[4], gis[4];
    #pragma unroll
    for (int ii = 0; ii < 4; ++ii) {
        int l = lv[ii];
        float ang = neg2pi * ((float)l * (1.0f / 4096.0f));
        float so, co;
        sincos_acc(ang, &so, &co);
        float opr = 1.0f + co, opi = so;     // 1 + Omega (exact subtraction sites)
        float omr = 1.0f - co, omi = -so;    // 1 - Omega
        float rinv = __fdividef(1.0f, opr * opr + opi * opi);
        crv[ii] =  2.0f * opr * rinv;
        civ[ii] = -2.0f * opi * rinv;
        grs[ii] = tos * ((omr * opr + omi * opi) * rinv);
        gis[ii] = tos * ((omi * opr - omr * opi) * rinv);
    }

    // packed accumulators per l: A (x-table) and B (y-table) per sum
    ull aA0[4] = {0,0,0,0}, aB0[4] = {0,0,0,0};   // k00
    ull aA1[4] = {0,0,0,0}, aB1[4] = {0,0,0,0};   // k01
    ull aA2[4] = {0,0,0,0}, aB2[4] = {0,0,0,0};   // k10
    ull a11[4] = {0,0,0,0};                       // k11

    #pragma unroll 4
    for (int n = 0; n < NST; ++n) {
        Tab0       t0 = sT0[n];
        ulonglong2 t1 = sT1[n];
        ulonglong2 t2 = sT2[n];
        ulonglong2 t3 = sT3[n];
        #pragma unroll
        for (int ii = 0; ii < 4; ++ii) {
            float dr = grs[ii] + t0.nlr;
            float di = gis[ii] + t0.nli;
            float s  = fmaf(dr, dr, di * di);
            float inv = __fdividef(1.0f, s);
            ull w = pk(dr * inv, di * inv);      // w = (p, q); 1/d = p - i*q
            aA0[ii] = fma2(t1.x, w, aA0[ii]);
            aB0[ii] = fma2(t1.y, w, aB0[ii]);
            aA1[ii] = fma2(t2.x, w, aA1[ii]);
            aB1[ii] = fma2(t2.y, w, aB1[ii]);
            aA2[ii] = fma2(t3.x, w, aA2[ii]);
            aB2[ii] = fma2(t3.y, w, aB2[ii]);
            a11[ii] = fma2(t0.pp2, w, a11[ii]);
        }
    }

    float2 kout[4];
    #pragma unroll
    for (int ii = 0; ii < 4; ++ii) {
        float xA, xB, yA, yB;
        // k00
        upk(aA0[ii], xA, xB); upk(aB0[ii], yA, yB);
        float a00r = xA + yB, a00i = yA - xB;
        // k01
        upk(aA1[ii], xA, xB); upk(aB1[ii], yA, yB);
        float a01r = xA + yB, a01i = yA - xB;
        // k10
        upk(aA2[ii], xA, xB); upk(aB2[ii], yA, yB);
        float a10r = xA + yB, a10i = yA - xB;
        // k11 = (acc.lo, -acc.hi)
        upk(a11[ii], xA, xB);
        float a11r = xA, a11i = -xB;

        // K = c * (k00 - k01 * k10 / (1 + k11))
        float tr = 1.0f + a11r, ti = a11i;
        float tinv = __fdividef(1.0f, tr * tr + ti * ti);
        float mr = a01r * a10r - a01i * a10i;
        float mi = a01r * a10i + a01i * a10r;
        float qr = (mr * tr + mi * ti) * tinv;
        float qi = (mi * tr - mr * ti) * tinv;
        float kr = a00r - qr, ki = a00i - qi;
        float cr_ = crv[ii], ci_ = civ[ii];
        kout[ii] = make_float2(cr_ * kr - ci_ * ki, cr_ * ki + ci_ * kr);
    }

    // Fused Hermitian part: Khat[l] = (K[l] + conj(K[-l])) * 0.5/L
    const float sc = 0.5f / 4096.0f;
    float2* Kh = g_Khat + ((size_t)h << 12);
    if (selfm) {
        Kh[lv[0]] = make_float2(2.0f * kout[0].x * sc, 0.0f);
        Kh[lv[1]] = make_float2(2.0f * kout[1].x * sc, 0.0f);
    } else {
        Kh[lv[0]] = make_float2((kout[0].x + kout[1].x) * sc,
                                (kout[0].y - kout[1].y) * sc);
        Kh[lv[1]] = make_float2((kout[1].x + kout[0].x) * sc,
                                (kout[1].y - kout[0].y) * sc);
    }
    Kh[lv[2]] = make_float2((kout[2].x + kout[3].x) * sc,
                            (kout[2].y - kout[3].y) * sc);
    Kh[lv[3]] = make_float2((kout[3].x + kout[2].x) * sc,
                            (kout[3].y - kout[2].y) * sc);
}

// ---------------------------------------------------------------------------
// Kernel 2: packed FFT convolution, radix-8 Stockham (4096 = 8^4).
// Register-fused ends: gmem->fwd0 in regs; fwd3+Khat+inv0 in regs;
// inv3->gmem in regs. 6 smem write+read rounds total.  (unchanged from R8)
// ---------------------------------------------------------------------------
#define SW8(i) ((i) + ((i) >> 3))   // pad swizzle for radix-8 access patterns
#define NPAD 4608                   // 4096 + 512

template <int DIR>
__device__ __forceinline__ void dft8(const float2* x, float2* out) {
    const float D = (float)DIR;
    float2 t0 = cadd(x[0], x[4]), t1 = csub(x[0], x[4]);
    float2 t2 = cadd(x[2], x[6]);
    float2 d26 = csub(x[2], x[6]);
    float2 t3 = make_float2(-D * d26.y, D * d26.x);
    float2 e0 = cadd(t0, t2), e1 = cadd(t1, t3);
    float2 e2 = csub(t0, t2), e3 = csub(t1, t3);

    float2 u0 = cadd(x[1], x[5]), u1 = csub(x[1], x[5]);
    float2 u2 = cadd(x[3], x[7]);
    float2 d37 = csub(x[3], x[7]);
    float2 u3 = make_float2(-D * d37.y, D * d37.x);
    float2 o0 = cadd(u0, u2), o1 = cadd(u1, u3);
    float2 o2 = csub(u0, u2), o3 = csub(u1, u3);

    const float C8 = 0.70710678118654752f;
    float2 q1 = make_float2(C8 * (o1.x - D * o1.y), C8 * (D * o1.x + o1.y));
    float2 q2 = make_float2(-D * o2.y, D * o2.x);
    float2 q3 = make_float2(C8 * (-o3.x - D * o3.y), C8 * (D * o3.x - o3.y));

    out[0] = cadd(e0, o0); out[4] = csub(e0, o0);
    out[1] = cadd(e1, q1); out[5] = csub(e1, q1);
    out[2] = cadd(e2, q2); out[6] = csub(e2, q2);
    out[3] = cadd(e3, q3); out[7] = csub(e3, q3);
}

template <int DIR, int K>
__device__ __forceinline__ void twiddle8(float2* out, int p) {
    if (K < 3) {
        const float base = (float)DIR * 6.2831853071795864f / (float)(4096 >> (3 * K));
        float sn, cs;
        __sincosf(base * (float)p, &sn, &cs);
        float2 w1 = make_float2(cs, sn);
        float2 w2 = cmul(w1, w1);
        float2 w3 = cmul(w2, w1);
        float2 w4 = cmul(w2, w2);
        float2 w5 = cmul(w3, w2);
        float2 w6 = cmul(w3, w3);
        float2 w7 = cmul(w4, w3);
        out[1] = cmul(out[1], w1); out[2] = cmul(out[2], w2);
        out[3] = cmul(out[3], w3); out[4] = cmul(out[4], w4);
        out[5] = cmul(out[5], w5); out[6] = cmul(out[6], w6);
        out[7] = cmul(out[7], w7);
    }
}

// middle stage: smem -> smem
template <int DIR, int K>
__device__ __forceinline__ void stage_smem(const float2* X, float2* Y, int j) {
    float2 x[8];
    #pragma unroll
    for (int r = 0; r < 8; ++r) x[r] = X[SW8(j + 512 * r)];
    float2 out[8];
    dft8<DIR>(x, out);
    twiddle8<DIR, K>(out, j >> (3 * K));
    const int s = 1 << (3 * K);
    int p = j >> (3 * K), q = j & (s - 1);
    int wb = q + 8 * s * p;
    #pragma unroll
    for (int r = 0; r < 8; ++r) Y[SW8(wb + s * r)] = out[r];
}

__global__ __launch_bounds__(512, 2)
void fftconv(const float* __restrict__ u, float* __restrict__ y) {
    extern __shared__ float2 smem[];
    float2* B0 = smem;
    float2* B1 = smem + NPAD;
    int j  = threadIdx.x;
    int h  = blockIdx.x & 255;
    int pb = blockIdx.x >> 8;

    size_t off0 = ((size_t)(2 * pb) * H_CH + (size_t)h) * LL;
    const float* u0 = u + off0;
    const float* u1 = u0 + (size_t)H_CH * LL;

    // fused: gmem load + forward stage 0 (regs) -> smem
    {
        float2 x[8], out[8];
        #pragma unroll
        for (int r = 0; r < 8; ++r) {
            int i = j + 512 * r;
            x[r] = make_float2(u0[i], u1[i]);
        }
        dft8<-1>(x, out);
        twiddle8<-1, 0>(out, j);
        #pragma unroll
        for (int r = 0; r < 8; ++r) B0[SW8(8 * j + r)] = out[r];
    }
    __syncthreads();
    stage_smem<-1, 1>(B0, B1, j); __syncthreads();
    stage_smem<-1, 2>(B1, B0, j); __syncthreads();

    // fused: forward stage 3 (natural order out) + Khat multiply + inverse
    // stage 0 (all in regs) -> smem
    {
        float2 x[8], f[8], out[8];
        #pragma unroll
        for (int r = 0; r < 8; ++r) x[r] = B0[SW8(j + 512 * r)];
        dft8<-1>(x, f);                       // k=3: no twiddle
        const float2* Kh = g_Khat + ((size_t)h << 12);
        #pragma unroll
        for (int r = 0; r < 8; ++r) f[r] = cmul(f[r], Kh[j + 512 * r]);
        dft8<1>(f, out);
        twiddle8<1, 0>(out, j);
        #pragma unroll
        for (int r = 0; r < 8; ++r) B1[SW8(8 * j + r)] = out[r];
    }
    __syncthreads();
    stage_smem<1, 1>(B1, B0, j); __syncthreads();
    stage_smem<1, 2>(B0, B1, j); __syncthreads();

    // fused: inverse stage 3 (regs) -> gmem (natural order, coalesced)
    {
        float2 x[8], out[8];
        #pragma unroll
        for (int r = 0; r < 8; ++r) x[r] = B1[SW8(j + 512 * r)];
        dft8<1>(x, out);                      // k=3: no twiddle
        float* y0 = y + off0;
        float* y1 = y0 + (size_t)H_CH * LL;
        #pragma unroll
        for (int r = 0; r < 8; ++r) {
            int i = j + 512 * r;
            y0[i] = out[r].x;
            y1[i] = out[r].y;
        }
    }
}

// ---------------------------------------------------------------------------
extern "C" void kernel_launch(void* const* d_in, const int* in_sizes, int n_in,
                              void* d_out, int out_size) {
    (void)in_sizes; (void)n_in; (void)out_size;
    const float* u   = (const float*)d_in[0];
    const float* Lre = (const float*)d_in[1];
    const float* Lim = (const float*)d_in[2];
    const float* Pre = (const float*)d_in[3];
    const float* Pim = (const float*)d_in[4];
    const float* Bre = (const float*)d_in[5];
    const float* Bim = (const float*)d_in[6];
    const float* Cre = (const float*)d_in[7];
    const float* Cim = (const float*)d_in[8];
    const float* lst = (const float*)d_in[9];
    float* y = (float*)d_out;

    const int smem_bytes = 2 * NPAD * (int)sizeof(float2);  // 73728
    cudaFuncSetAttribute(fftconv, cudaFuncAttributeMaxDynamicSharedMemorySize, smem_bytes);

    kgen<<<H_CH * 4, 256>>>(Lre, Lim, Pre, Pim, Bre, Bim, Cre, Cim, lst);
    fftconv<<<(NBATCH / 2) * H_CH, 512, smem_bytes>>>(u, y);
}

// round 12
// speedup vs baseline: 1.0994x; 1.0994x over previous
#include <cuda_runtime.h>
#include <cstdint>

#define H_CH 256
#define NST  64
#define LL   4096
#define NBATCH 16

typedef unsigned long long ull;

// Scratch (device global: allocation-free rule)
__device__ float2 g_Khat[H_CH * LL];   // hermitian part of K, pre-scaled by 1/L

__device__ __forceinline__ float2 cmul(float2 a, float2 b) {
    return make_float2(a.x * b.x - a.y * b.y, a.x * b.y + a.y * b.x);
}
__device__ __forceinline__ float2 cadd(float2 a, float2 b) {
    return make_float2(a.x + b.x, a.y + b.y);
}
__device__ __forceinline__ float2 csub(float2 a, float2 b) {
    return make_float2(a.x - b.x, a.y - b.y);
}

// ---- packed f32x2 helpers ----
__device__ __forceinline__ ull pk(float lo, float hi) {
    ull r; asm("mov.b64 %0,{%1,%2};" : "=l"(r) : "f"(lo), "f"(hi)); return r;
}
__device__ __forceinline__ void upk(ull v, float& lo, float& hi) {
    asm("mov.b64 {%0,%1},%2;" : "=f"(lo), "=f"(hi) : "l"(v));
}
__device__ __forceinline__ ull fma2(ull a, ull b, ull c) {
    ull d; asm("fma.rn.f32x2 %0,%1,%2,%3;" : "=l"(d) : "l"(a), "l"(b), "l"(c)); return d;
}
__device__ __forceinline__ ull add2(ull a, ull b) {
    ull d; asm("add.rn.f32x2 %0,%1,%2;" : "=l"(d) : "l"(a), "l"(b)); return d;
}
__device__ __forceinline__ ull mul2(ull a, ull b) {
    ull d; asm("mul.rn.f32x2 %0,%1,%2;" : "=l"(d) : "l"(a), "l"(b)); return d;
}

// Correctly-rounded float sin/cos via double polynomial.
// Needed so 1+cos / 1-cos cancellation sites match the float32 reference bitwise.
// Valid for ang in [-2*pi, 0].
__device__ __forceinline__ void sincos_acc(float angf, float* s, float* c) {
    double x  = (double)angf;
    double kd = rint(x * 0.63661977236758134308);   // x / (pi/2)
    double r  = x - kd * 1.5707963267948966;
    r        -= kd * 6.123233995736766e-17;
    int q = (int)kd;
    double r2 = r * r;
    double sr = r * (1.0 + r2 * (-1.6666666666666666e-01 + r2 * (8.3333333333333332e-03
                 + r2 * (-1.9841269841269841e-04 + r2 * 2.7557319223985893e-06))));
    double cr = 1.0 + r2 * (-0.5 + r2 * (4.1666666666666664e-02
                 + r2 * (-1.3888888888888889e-03 + r2 * (2.4801587301587302e-05
                 - r2 * 2.7557319223985888e-07))));
    double ss, cc;
    switch (q & 3) {
        case 0:  ss =  sr; cc =  cr; break;
        case 1:  ss =  cr; cc = -sr; break;
        case 2:  ss = -sr; cc = -cr; break;
        default: ss = -cr; cc =  sr; break;
    }
    *s = (float)ss;
    *c = (float)cc;
}

// ---------------------------------------------------------------------------
// Kernel 1: S4 DPLR frequency-domain kernel + FUSED Hermitian part.
// (REVERTED to the R9-measured-best version: mirror-pair (gid, 4096-gid),
//  2 l-values/thread, float4 tables, packed f32x2 accumulation with a single
//  packed multiplier w = (p, q) against pre-broadcast (x,x)/(y,y) tables.)
// ---------------------------------------------------------------------------
__global__ __launch_bounds__(256)
void kgen(const float* __restrict__ Lre, const float* __restrict__ Lim,
          const float* __restrict__ Pre, const float* __restrict__ Pim,
          const float* __restrict__ Bre, const float* __restrict__ Bim,
          const float* __restrict__ Cre, const float* __restrict__ Cim,
          const float* __restrict__ lstep) {
    __shared__ float4 sA[NST];  // (-lam.re, -lam.im, pp, pp)       pp = |P|^2
    __shared__ float4 sB[NST];  // (cb.x, cb.x, cb.y, cb.y)   cb = conj(C)*B
    __shared__ float4 sC[NST];  // (cp.x, cp.x, cp.y, cp.y)   cp = conj(C)*P
    __shared__ float4 sD[NST];  // (pb.x, pb.x, pb.y, pb.y)   pb = conj(P)*B
    __shared__ float  s_tos;

    int h   = blockIdx.x >> 3;
    int seg = blockIdx.x & 7;
    int tid = threadIdx.x;

    if (tid < NST) {
        int idx = h * NST + tid;
        float lr = Lre[idx], li = Lim[idx];
        float pr = Pre[idx], pi = Pim[idx];
        float br = Bre[idx], bi = Bim[idx];
        float cr = Cre[idx], ci = Cim[idx];
        float cbx = cr * br + ci * bi, cby = cr * bi - ci * br;
        float cpx = cr * pr + ci * pi, cpy = cr * pi - ci * pr;
        float pbx = pr * br + pi * bi, pby = pr * bi - pi * br;
        float pp  = pr * pr + pi * pi;
        sA[tid] = make_float4(-lr, -li, pp, pp);
        sB[tid] = make_float4(cbx, cbx, cby, cby);
        sC[tid] = make_float4(cpx, cpx, cpy, cpy);
        sD[tid] = make_float4(pbx, pbx, pby, pby);
    }
    if (tid == 0) s_tos = 2.0f / __expf(lstep[h]);
    __syncthreads();
    float tos = s_tos;

    const float neg2pi = (float)(-6.283185307179586);

    // mirror-pair l mapping: (gid, 4096-gid); gid==0 -> (0, 2048)
    int gid = seg * 256 + tid;          // 0..2047 per h
    int lv[2];
    lv[0] = gid;
    lv[1] = (gid == 0) ? 2048 : (LL - gid);
    bool selfm = (gid == 0);            // both bins self-mirrored

    float crv[2], civ[2];               // c = 2/(1+Omega)
    ull   gpk[2];
    #pragma unroll
    for (int ii = 0; ii < 2; ++ii) {
        int l = lv[ii];
        float ang = neg2pi * ((float)l * (1.0f / 4096.0f));
        float so, co;
        sincos_acc(ang, &so, &co);
        float opr = 1.0f + co, opi = so;     // 1 + Omega (exact subtraction sites)
        float omr = 1.0f - co, omi = -so;    // 1 - Omega
        float rinv = __fdividef(1.0f, opr * opr + opi * opi);
        crv[ii] =  2.0f * opr * rinv;
        civ[ii] = -2.0f * opi * rinv;
        float gr = tos * ((omr * opr + omi * opi) * rinv);
        float gi = tos * ((omi * opr - omr * opi) * rinv);
        gpk[ii] = pk(gr, gi);
    }

    // packed accumulators: per l, per sum: A (x-table) and B (y-table)
    ull aA0[2] = {0,0}, aB0[2] = {0,0};   // k00
    ull aA1[2] = {0,0}, aB1[2] = {0,0};   // k01
    ull aA2[2] = {0,0}, aB2[2] = {0,0};   // k10
    ull a11[2] = {0,0};                   // k11 (pp,pp)*w

    #pragma unroll 8
    for (int n = 0; n < NST; ++n) {
        float4 fa = sA[n], fb = sB[n], fc = sC[n], fd = sD[n];
        ull nlam = pk(fa.x, fa.y);
        ull pp2  = pk(fa.z, fa.w);
        ull bx   = pk(fb.x, fb.y), by = pk(fb.z, fb.w);
        ull cx   = pk(fc.x, fc.y), cy = pk(fc.z, fc.w);
        ull dx   = pk(fd.x, fd.y), dy = pk(fd.z, fd.w);
        #pragma unroll
        for (int ii = 0; ii < 2; ++ii) {
            ull d = add2(gpk[ii], nlam);         // d = g - lambda  (dr, di)
            ull sq = mul2(d, d);                 // (dr^2, di^2)
            float s0, s1; upk(sq, s0, s1);
            float inv = __fdividef(1.0f, s0 + s1);
            ull w = mul2(d, pk(inv, inv));       // w = (p, q); 1/d = p - i*q
            aA0[ii] = fma2(bx, w, aA0[ii]);
            aB0[ii] = fma2(by, w, aB0[ii]);
            aA1[ii] = fma2(cx, w, aA1[ii]);
            aB1[ii] = fma2(cy, w, aB1[ii]);
            aA2[ii] = fma2(dx, w, aA2[ii]);
            aB2[ii] = fma2(dy, w, aB2[ii]);
            a11[ii] = fma2(pp2, w, a11[ii]);
        }
    }

    float2 kout[2];
    #pragma unroll
    for (int ii = 0; ii < 2; ++ii) {
        float xA, xB, yA, yB;
        // k00
        upk(aA0[ii], xA, xB); upk(aB0[ii], yA, yB);
        float a00r = xA + yB, a00i = yA - xB;
        // k01
        upk(aA1[ii], xA, xB); upk(aB1[ii], yA, yB);
        float a01r = xA + yB, a01i = yA - xB;
        // k10
        upk(aA2[ii], xA, xB); upk(aB2[ii], yA, yB);
        float a10r = xA + yB, a10i = yA - xB;
        // k11 = (acc.lo, -acc.hi)
        upk(a11[ii], xA, xB);
        float a11r = xA, a11i = -xB;

        // K = c * (k00 - k01 * k10 / (1 + k11))
        float tr = 1.0f + a11r, ti = a11i;
        float tinv = __fdividef(1.0f, tr * tr + ti * ti);
        float mr = a01r * a10r - a01i * a10i;
        float mi = a01r * a10i + a01i * a10r;
        float qr = (mr * tr + mi * ti) * tinv;
        float qi = (mi * tr - mr * ti) * tinv;
        float kr = a00r - qr, ki = a00i - qi;
        float cr_ = crv[ii], ci_ = civ[ii];
        kout[ii] = make_float2(cr_ * kr - ci_ * ki, cr_ * ki + ci_ * kr);
    }

    // Fused Hermitian part: Khat[l] = (K[l] + conj(K[-l])) * 0.5/L
    const float sc = 0.5f / 4096.0f;
    float2* Kh = g_Khat + ((size_t)h << 12);
    if (selfm) {
        Kh[lv[0]] = make_float2(2.0f * kout[0].x * sc, 0.0f);
        Kh[lv[1]] = make_float2(2.0f * kout[1].x * sc, 0.0f);
    } else {
        Kh[lv[0]] = make_float2((kout[0].x + kout[1].x) * sc,
                                (kout[0].y - kout[1].y) * sc);
        Kh[lv[1]] = make_float2((kout[1].x + kout[0].x) * sc,
                                (kout[1].y - kout[0].y) * sc);
    }
}

// ---------------------------------------------------------------------------
// Kernel 2: packed FFT convolution, radix-8 Stockham (4096 = 8^4).
// Register-fused ends (6 smem rounds) + NEW conflict-free XOR swizzle:
//   SW(i) = i ^ ((i>>3) & 15)
// Bijective on [0,4096) (no padding -> 64KB smem) and bank-conflict-free for
// EVERY access pattern in this kernel (consecutive reads, stride-8 writes,
// q+64p writes, consecutive stage-2 writes) at float2/8B granularity.
// ---------------------------------------------------------------------------
#define SW(i) ((i) ^ (((i) >> 3) & 15))
#define NPAD 4096

template <int DIR>
__device__ __forceinline__ void dft8(const float2* x, float2* out) {
    const float D = (float)DIR;
    float2 t0 = cadd(x[0], x[4]), t1 = csub(x[0], x[4]);
    float2 t2 = cadd(x[2], x[6]);
    float2 d26 = csub(x[2], x[6]);
    float2 t3 = make_float2(-D * d26.y, D * d26.x);
    float2 e0 = cadd(t0, t2), e1 = cadd(t1, t3);
    float2 e2 = csub(t0, t2), e3 = csub(t1, t3);

    float2 u0 = cadd(x[1], x[5]), u1 = csub(x[1], x[5]);
    float2 u2 = cadd(x[3], x[7]);
    float2 d37 = csub(x[3], x[7]);
    float2 u3 = make_float2(-D * d37.y, D * d37.x);
    float2 o0 = cadd(u0, u2), o1 = cadd(u1, u3);
    float2 o2 = csub(u0, u2), o3 = csub(u1, u3);

    const float C8 = 0.70710678118654752f;
    float2 q1 = make_float2(C8 * (o1.x - D * o1.y), C8 * (D * o1.x + o1.y));
    float2 q2 = make_float2(-D * o2.y, D * o2.x);
    float2 q3 = make_float2(C8 * (-o3.x - D * o3.y), C8 * (D * o3.x - o3.y));

    out[0] = cadd(e0, o0); out[4] = csub(e0, o0);
    out[1] = cadd(e1, q1); out[5] = csub(e1, q1);
    out[2] = cadd(e2, q2); out[6] = csub(e2, q2);
    out[3] = cadd(e3, q3); out[7] = csub(e3, q3);
}

template <int DIR, int K>
__device__ __forceinline__ void twiddle8(float2* out, int p) {
    if (K < 3) {
        const float base = (float)DIR * 6.2831853071795864f / (float)(4096 >> (3 * K));
        float sn, cs;
        __sincosf(base * (float)p, &sn, &cs);
        float2 w1 = make_float2(cs, sn);
        float2 w2 = cmul(w1, w1);
        float2 w3 = cmul(w2, w1);
        float2 w4 = cmul(w2, w2);
        float2 w5 = cmul(w3, w2);
        float2 w6 = cmul(w3, w3);
        float2 w7 = cmul(w4, w3);
        out[1] = cmul(out[1], w1); out[2] = cmul(out[2], w2);
        out[3] = cmul(out[3], w3); out[4] = cmul(out[4], w4);
        out[5] = cmul(out[5], w5); out[6] = cmul(out[6], w6);
        out[7] = cmul(out[7], w7);
    }
}

// middle stage: smem -> smem
template <int DIR, int K>
__device__ __forceinline__ void stage_smem(const float2* X, float2* Y, int j) {
    float2 x[8];
    #pragma unroll
    for (int r = 0; r < 8; ++r) x[r] = X[SW(j + 512 * r)];
    float2 out[8];
    dft8<DIR>(x, out);
    twiddle8<DIR, K>(out, j >> (3 * K));
    const int s = 1 << (3 * K);
    int p = j >> (3 * K), q = j & (s - 1);
    int wb = q + 8 * s * p;
    #pragma unroll
    for (int r = 0; r < 8; ++r) Y[SW(wb + s * r)] = out[r];
}

__global__ __launch_bounds__(512, 2)
void fftconv(const float* __restrict__ u, float* __restrict__ y) {
    extern __shared__ float2 smem[];
    float2* B0 = smem;
    float2* B1 = smem + NPAD;
    int j  = threadIdx.x;
    int h  = blockIdx.x & 255;
    int pb = blockIdx.x >> 8;

    size_t off0 = ((size_t)(2 * pb) * H_CH + (size_t)h) * LL;
    const float* u0 = u + off0;
    const float* u1 = u0 + (size_t)H_CH * LL;

    // fused: gmem load + forward stage 0 (regs) -> smem
    {
        float2 x[8], out[8];
        #pragma unroll
        for (int r = 0; r < 8; ++r) {
            int i = j + 512 * r;
            x[r] = make_float2(u0[i], u1[i]);
        }
        dft8<-1>(x, out);
        twiddle8<-1, 0>(out, j);
        #pragma unroll
        for (int r = 0; r < 8; ++r) B0[SW(8 * j + r)] = out[r];
    }
    __syncthreads();
    stage_smem<-1, 1>(B0, B1, j); __syncthreads();
    stage_smem<-1, 2>(B1, B0, j); __syncthreads();

    // fused: forward stage 3 (natural order out) + Khat multiply + inverse
    // stage 0 (all in regs) -> smem
    {
        float2 x[8], f[8], out[8];
        #pragma unroll
        for (int r = 0; r < 8; ++r) x[r] = B0[SW(j + 512 * r)];
        dft8<-1>(x, f);                       // k=3: no twiddle
        const float2* Kh = g_Khat + ((size_t)h << 12);
        #pragma unroll
        for (int r = 0; r < 8; ++r) f[r] = cmul(f[r], Kh[j + 512 * r]);
        dft8<1>(f, out);
        twiddle8<1, 0>(out, j);
        #pragma unroll
        for (int r = 0; r < 8; ++r) B1[SW(8 * j + r)] = out[r];
    }
    __syncthreads();
    stage_smem<1, 1>(B1, B0, j); __syncthreads();
    stage_smem<1, 2>(B0, B1, j); __syncthreads();

    // fused: inverse stage 3 (regs) -> gmem (natural order, coalesced)
    {
        float2 x[8], out[8];
        #pragma unroll
        for (int r = 0; r < 8; ++r) x[r] = B1[SW(j + 512 * r)];
        dft8<1>(x, out);                      // k=3: no twiddle
        float* y0 = y + off0;
        float* y1 = y0 + (size_t)H_CH * LL;
        #pragma unroll
        for (int r = 0; r < 8; ++r) {
            int i = j + 512 * r;
            y0[i] = out[r].x;
            y1[i] = out[r].y;
        }
    }
}

// ---------------------------------------------------------------------------
extern "C" void kernel_launch(void* const* d_in, const int* in_sizes, int n_in,
                              void* d_out, int out_size) {
    (void)in_sizes; (void)n_in; (void)out_size;
    const float* u   = (const float*)d_in[0];
    const float* Lre = (const float*)d_in[1];
    const float* Lim = (const float*)d_in[2];
    const float* Pre = (const float*)d_in[3];
    const float* Pim = (const float*)d_in[4];
    const float* Bre = (const float*)d_in[5];
    const float* Bim = (const float*)d_in[6];
    const float* Cre = (const float*)d_in[7];
    const float* Cim = (const float*)d_in[8];
    const float* lst = (const float*)d_in[9];
    float* y = (float*)d_out;

    const int smem_bytes = 2 * NPAD * (int)sizeof(float2);  // 65536
    cudaFuncSetAttribute(fftconv, cudaFuncAttributeMaxDynamicSharedMemorySize, smem_bytes);

    kgen<<<H_CH * 8, 256>>>(Lre, Lim, Pre, Pim, Bre, Bim, Cre, Cim, lst);
    fftconv<<<(NBATCH / 2) * H_CH, 512, smem_bytes>>>(u, y);
}